// round 16
// baseline (speedup 1.0000x reference)
#include <cuda_runtime.h>
#include <math.h>

#define B_    64
#define S_    512
#define E_    256
#define H_    512
#define NCTA  128
#define NTHR  320

// ---------------- device scratch (static; no allocation) ----------------
__device__ float g_upT[(long long)S_ * 2048 * B_];   // [s][g][b]  256 MB
__device__ float g_decT[S_ * B_];                    // [s][b]
__device__ float g_h[2][H_ * B_];                    // [par][u][b]
__device__ float g_c[2][H_ * B_];
__device__ volatile unsigned g_bar_gen;
__device__ unsigned g_bar_cnt;

// ---------------- helpers ----------------
__device__ __forceinline__ float sigf(float x) { return 1.0f / (1.0f + __expf(-x)); }
__device__ __forceinline__ float tanh_fast(float x) {
    float e = __expf(2.0f * x);
    return 1.0f - 2.0f / (e + 1.0f);
}

__device__ __forceinline__ void grid_barrier() {
    __threadfence();           // make this CTA's global stores device-visible
    __syncthreads();
    if (threadIdx.x == 0) {
        unsigned my = g_bar_gen;
        if (atomicAdd(&g_bar_cnt, 1u) == (unsigned)(NCTA - 1)) {
            g_bar_cnt = 0;
            __threadfence();
            g_bar_gen = my + 1u;        // release
        } else {
            while (g_bar_gen == my) { } // volatile spin (L2)
        }
    }
    __syncthreads();
}

// ---------------- prep: decay transpose + zero states ----------------
__global__ void prep_kernel(const float* __restrict__ ts) {
    int i = blockIdx.x * blockDim.x + threadIdx.x;
    if (i < S_ * B_) {
        int s = i >> 6, b = i & 63;
        g_decT[i] = 1.0f / logf(2.718281828459045f + ts[b * S_ + s]);
        g_h[0][i] = 0.0f; g_h[1][i] = 0.0f;
        g_c[0][i] = 0.0f; g_c[1][i] = 0.0f;
    }
}

// ---------------- u_proj GEMM: [32768 x 256] @ [256 x 2048]^T -> g_upT[s][g][b] ----------------
#define BM 128
#define BN 128
#define BK 16
__global__ __launch_bounds__(256) void uproj_gemm(const float* __restrict__ X,
                                                  const float* __restrict__ U,
                                                  const float* __restrict__ Ub) {
    __shared__ float As[BK][BM + 4];
    __shared__ float Bs[BK][BN + 4];
    int tid = threadIdx.x;
    int m0 = blockIdx.x * BM;     // m' = s*64 + b
    int n0 = blockIdx.y * BN;
    int tm = (tid >> 4) << 3;     // 0..120
    int tn = (tid & 15) << 3;     // 0..120

    float acc[8][8];
#pragma unroll
    for (int i = 0; i < 8; i++)
#pragma unroll
        for (int j = 0; j < 8; j++) acc[i][j] = 0.0f;

    for (int k0 = 0; k0 < E_; k0 += BK) {
#pragma unroll
        for (int it = 0; it < 2; it++) {
            int t = tid + it * 256;        // 0..511
            int row = t >> 2;              // 0..127
            int kq = (t & 3) << 2;         // 0,4,8,12
            int mp = m0 + row;
            int bb = mp & 63, ssx = mp >> 6;
            float4 va = *(const float4*)(X + ((long long)bb * S_ + ssx) * E_ + k0 + kq);
            As[kq + 0][row] = va.x; As[kq + 1][row] = va.y;
            As[kq + 2][row] = va.z; As[kq + 3][row] = va.w;
            float4 vb = *(const float4*)(U + (long long)(n0 + row) * E_ + k0 + kq);
            Bs[kq + 0][row] = vb.x; Bs[kq + 1][row] = vb.y;
            Bs[kq + 2][row] = vb.z; Bs[kq + 3][row] = vb.w;
        }
        __syncthreads();
#pragma unroll
        for (int k = 0; k < BK; k++) {
            float a[8], b[8];
            *(float4*)&a[0] = *(const float4*)&As[k][tm];
            *(float4*)&a[4] = *(const float4*)&As[k][tm + 4];
            *(float4*)&b[0] = *(const float4*)&Bs[k][tn];
            *(float4*)&b[4] = *(const float4*)&Bs[k][tn + 4];
#pragma unroll
            for (int i = 0; i < 8; i++)
#pragma unroll
                for (int j = 0; j < 8; j++) acc[i][j] += a[i] * b[j];
        }
        __syncthreads();
    }

    int ssx = (m0 + tm) >> 6;
    int b0  = (m0 + tm) & 63;     // 8 consecutive b, same s
#pragma unroll
    for (int j = 0; j < 8; j++) {
        int g = n0 + tn + j;
        float ub = Ub[g];
        float4 v0, v1;
        v0.x = acc[0][j] + ub; v0.y = acc[1][j] + ub; v0.z = acc[2][j] + ub; v0.w = acc[3][j] + ub;
        v1.x = acc[4][j] + ub; v1.y = acc[5][j] + ub; v1.z = acc[6][j] + ub; v1.w = acc[7][j] + ub;
        float* dst = &g_upT[((long long)ssx * 2048 + g) * 64 + b0];
        *(float4*)dst = v0;
        *(float4*)(dst + 4) = v1;
    }
}

// ---------------- persistent recurrent kernel ----------------
// SMEM: ws[512][20] | hs[4][32][64] | cs[4][32][64] | red[4][20][64] | hn[64][4] | cn[64][4]
#define SM_WS   0
#define SM_HS   (512 * 20)
#define SM_CS   (SM_HS + 4 * 32 * 64)
#define SM_RED  (SM_CS + 4 * 32 * 64)
#define SM_HN   (SM_RED + 4 * 20 * 64)
#define SM_CN   (SM_HN + 64 * 4)
#define SM_FLOATS (SM_CN + 64 * 4)

__global__ __launch_bounds__(NTHR, 1) void step_kernel(
    const float* __restrict__ Wall, const float* __restrict__ Wallb,
    const float* __restrict__ Wd,   const float* __restrict__ Wdb,
    float* __restrict__ out)
{
    extern __shared__ float sm[];
    float* ws  = sm + SM_WS;
    float* hs  = sm + SM_HS;
    float* cs  = sm + SM_CS;
    float* red = sm + SM_RED;
    float* hn  = sm + SM_HN;
    float* cn  = sm + SM_CN;

    const int tid  = threadIdx.x;
    const int cta  = blockIdx.x;
    const int kgrp = tid / 80;          // 0..3
    const int r80  = tid % 80;
    const int rgrp = r80 / 16;          // 0..4   (0..3 -> h rows, 4 -> c rows)
    const int bgrp = r80 % 16;          // 0..15
    const int u0   = cta * 4;           // this CTA's 4 hidden units

    // ---- load this CTA's 20 weight rows into SMEM (once) ----
    for (int i = tid; i < 20 * 512; i += NTHR) {
        int rloc = i >> 9, k = i & 511;
        float w;
        if (rloc < 16) w = Wall[((rloc >> 2) * 512 + u0 + (rloc & 3)) * 512 + k];
        else           w = Wd[(u0 + (rloc - 16)) * 512 + k];
        ws[k * 20 + rloc] = w;
    }

    // ---- epilogue cell ownership: thread t<256 owns (b = t&63, ul = t>>6) ----
    const int  eb  = tid & 63;
    const int  eul = tid >> 6;
    const bool ep  = (tid < 256);
    float c_reg = 0.0f;
    float bf = 0, bi = 0, bo = 0, bct = 0, bd = 0;
    if (ep) {
        int u = u0 + eul;
        bf  = Wallb[u];
        bi  = Wallb[512 + u];
        bo  = Wallb[1024 + u];
        bct = Wallb[1536 + u];
        bd  = Wdb[u];
    }
    __syncthreads();

    const float* apool = (rgrp < 4) ? hs : cs;
    const int aoff = kgrp * 32 * 64 + bgrp * 4;
    const int woff = rgrp * 4;

    for (int s = 0; s < S_; s++) {
        const int par = s & 1;
        const float* gh = g_h[par];
        const float* gc = g_c[par];

        float acc[4][4];
#pragma unroll
        for (int i = 0; i < 4; i++)
#pragma unroll
            for (int j = 0; j < 4; j++) acc[i][j] = 0.0f;

        for (int kc = 0; kc < 128; kc += 32) {
            __syncthreads();
            // stage hT/cT chunk: [4 kgrp][32 k][64 b], bypass L1 (cross-CTA data)
            for (int i = tid; i < 2048; i += NTHR) {
                int kg = i >> 9, rem = i & 511;
                int kk = rem >> 4, b4 = (rem & 15) << 2;
                int gidx = (kg * 128 + kc + kk) * 64 + b4;
                *(float4*)&hs[kg * 2048 + kk * 64 + b4] = __ldcg((const float4*)&gh[gidx]);
                *(float4*)&cs[kg * 2048 + kk * 64 + b4] = __ldcg((const float4*)&gc[gidx]);
            }
            __syncthreads();
#pragma unroll
            for (int kk = 0; kk < 32; kk++) {
                float4 a4 = *(const float4*)&apool[aoff + kk * 64];
                float4 w4 = *(const float4*)&ws[(kgrp * 128 + kc + kk) * 20 + woff];
                float av[4] = {a4.x, a4.y, a4.z, a4.w};
                float wv[4] = {w4.x, w4.y, w4.z, w4.w};
#pragma unroll
                for (int i = 0; i < 4; i++)
#pragma unroll
                    for (int j = 0; j < 4; j++) acc[i][j] += av[i] * wv[j];
            }
        }

        // ---- K-group reduce via SMEM ----
#pragma unroll
        for (int j = 0; j < 4; j++) {
            float4 v;
            v.x = acc[0][j]; v.y = acc[1][j]; v.z = acc[2][j]; v.w = acc[3][j];
            *(float4*)&red[(kgrp * 20 + rgrp * 4 + j) * 64 + bgrp * 4] = v;
        }
        __syncthreads();

        // ---- fused LSTM update epilogue ----
        if (ep) {
            int u = u0 + eul;
            float gsum[5];
#pragma unroll
            for (int g5 = 0; g5 < 5; g5++) {
                int rl = (g5 < 4) ? (g5 * 4 + eul) : (16 + eul);
                float v = 0.0f;
#pragma unroll
                for (int kg = 0; kg < 4; kg++) v += red[(kg * 20 + rl) * 64 + eb];
                gsum[g5] = v;
            }
            float dec = g_decT[s * 64 + eb];
            const float* up = &g_upT[(long long)s * 2048 * 64];
            float upf = up[(0 * 512 + u) * 64 + eb];
            float upi = up[(1 * 512 + u) * 64 + eb];
            float upo = up[(2 * 512 + u) * 64 + eb];
            float upc = up[(3 * 512 + u) * 64 + eb];

            float cs1  = tanh_fast(gsum[4] + bd);
            float cadj = (c_reg - cs1) + cs1 * dec;
            float f  = sigf(gsum[0] + bf + upf);
            float ii = sigf(gsum[1] + bi + upi);
            float oo = sigf(gsum[2] + bo + upo);
            float ct = tanh_fast(gsum[3] + bct + upc);
            float cnew = f * cadj + ii * ct;
            float hnew = oo * tanh_fast(cnew);
            c_reg = cnew;

            int par2 = par ^ 1;
            __stcg(&g_h[par2][u * 64 + eb], hnew);
            __stcg(&g_c[par2][u * 64 + eb], cnew);
            hn[eb * 4 + eul] = hnew;
            cn[eb * 4 + eul] = cnew;
        }
        __syncthreads();

        // coalesced-ish output writes via SMEM bounce (16B per store)
        if (tid < 64) {
            float4 hv = *(float4*)&hn[tid * 4];
            *(float4*)&out[((long long)tid * S_ + s) * H_ + u0] = hv;
            if (s == S_ - 1) {
                float4 cv = *(float4*)&cn[tid * 4];
                *(float4*)&out[(long long)B_ * S_ * H_ + (long long)tid * H_ + u0] = hv;
                *(float4*)&out[(long long)B_ * S_ * H_ + (long long)B_ * H_ + (long long)tid * H_ + u0] = cv;
            }
        }

        grid_barrier();   // h/c parity buffers published for next step
    }
}

// ---------------- launcher ----------------
extern "C" void kernel_launch(void* const* d_in, const int* in_sizes, int n_in,
                              void* d_out, int out_size) {
    const float* inputs = (const float*)d_in[0];
    const float* ts     = (const float*)d_in[1];
    const float* Wall   = (const float*)d_in[2];
    const float* Wallb  = (const float*)d_in[3];
    const float* U      = (const float*)d_in[4];
    const float* Ub     = (const float*)d_in[5];
    const float* Wd     = (const float*)d_in[6];
    const float* Wdb    = (const float*)d_in[7];
    float* out = (float*)d_out;

    prep_kernel<<<(S_ * B_ + 255) / 256, 256>>>(ts);

    dim3 ggrid(32768 / BM, 2048 / BN);
    uproj_gemm<<<ggrid, 256>>>(inputs, U, Ub);

    static const size_t smem_bytes = (size_t)SM_FLOATS * sizeof(float);  // ~129 KB
    cudaFuncSetAttribute(step_kernel, cudaFuncAttributeMaxDynamicSharedMemorySize,
                         (int)smem_bytes);
    step_kernel<<<NCTA, NTHR, smem_bytes>>>(Wall, Wallb, Wd, Wdb, out);
}

// round 17
// speedup vs baseline: 1.8166x; 1.8166x over previous
#include <cuda_runtime.h>
#include <math.h>
#include <cstdint>

#define B_    64
#define S_    512
#define E_    256
#define H_    512
#define NCTA  128
#define NTHR  320

// ---------------- device scratch (static; no allocation) ----------------
__device__ float g_upT[(long long)S_ * 2048 * B_];   // [s][g][b]  256 MB
__device__ float g_decT[S_ * B_];                    // [s][b]
__device__ float g_h[2][H_ * B_];                    // [par][k][b]
__device__ float g_c[2][H_ * B_];
__device__ volatile unsigned g_bar_gen;
__device__ unsigned g_bar_cnt;

// ---------------- helpers ----------------
__device__ __forceinline__ float sigf(float x) { return 1.0f / (1.0f + __expf(-x)); }
__device__ __forceinline__ float tanh_fast(float x) {
    float e = __expf(2.0f * x);
    return 1.0f - 2.0f / (e + 1.0f);
}

__device__ __forceinline__ unsigned smem_u32(const void* p) {
    return (unsigned)__cvta_generic_to_shared(p);
}

__device__ __forceinline__ void mbar_init(unsigned mbar, unsigned count) {
    asm volatile("mbarrier.init.shared.b64 [%0], %1;" :: "r"(mbar), "r"(count) : "memory");
}
__device__ __forceinline__ void mbar_expect(unsigned mbar, unsigned bytes) {
    asm volatile("mbarrier.arrive.expect_tx.shared.b64 _, [%0], %1;" :: "r"(mbar), "r"(bytes) : "memory");
}
__device__ __forceinline__ void mbar_wait(unsigned mbar, unsigned phase) {
    asm volatile(
        "{\n\t"
        ".reg .pred P;\n\t"
        "LW%=:\n\t"
        "mbarrier.try_wait.parity.shared.b64 P, [%0], %1;\n\t"
        "@P bra.uni LD%=;\n\t"
        "bra.uni LW%=;\n\t"
        "LD%=:\n\t"
        "}"
        :: "r"(mbar), "r"(phase) : "memory");
}
__device__ __forceinline__ void bulk_g2s(unsigned dst, const void* src, unsigned bytes, unsigned mbar) {
    asm volatile(
        "cp.async.bulk.shared::cluster.global.mbarrier::complete_tx::bytes [%0], [%1], %2, [%3];"
        :: "r"(dst), "l"(src), "r"(bytes), "r"(mbar) : "memory");
}

#define FMA2(acc, a, b) \
    asm volatile("fma.rn.f32x2 %0, %1, %2, %0;" : "+l"(acc) : "l"(a), "l"(b))
#define PACKDUP(dst, x) \
    asm volatile("mov.b64 %0, {%1, %1};" : "=l"(dst) : "f"(x))
#define UNPACK2(lo, hi, v) \
    asm volatile("mov.b64 {%0, %1}, %2;" : "=f"(lo), "=f"(hi) : "l"(v))

__device__ __forceinline__ void grid_barrier() {
    __threadfence();
    __syncthreads();
    if (threadIdx.x == 0) {
        unsigned my = g_bar_gen;
        if (atomicAdd(&g_bar_cnt, 1u) == (unsigned)(NCTA - 1)) {
            g_bar_cnt = 0;
            __threadfence();
            g_bar_gen = my + 1u;
        } else {
            while (g_bar_gen == my) { }
        }
    }
    __syncthreads();
}

// ---------------- prep: decay transpose + zero states ----------------
__global__ void prep_kernel(const float* __restrict__ ts) {
    int i = blockIdx.x * blockDim.x + threadIdx.x;
    if (i < S_ * B_) {
        int s = i >> 6, b = i & 63;
        g_decT[i] = 1.0f / logf(2.718281828459045f + ts[b * S_ + s]);
        g_h[0][i] = 0.0f; g_h[1][i] = 0.0f;
        g_c[0][i] = 0.0f; g_c[1][i] = 0.0f;
    }
}

// ---------------- u_proj GEMM: [32768 x 256] @ [256 x 2048]^T -> g_upT[s][g][b] ----------------
#define BM 128
#define BN 128
#define BK 16
__global__ __launch_bounds__(256) void uproj_gemm(const float* __restrict__ X,
                                                  const float* __restrict__ U,
                                                  const float* __restrict__ Ub) {
    __shared__ float As[BK][BM + 4];
    __shared__ float Bs[BK][BN + 4];
    int tid = threadIdx.x;
    int m0 = blockIdx.x * BM;     // m' = s*64 + b
    int n0 = blockIdx.y * BN;
    int tm = (tid >> 4) << 3;     // 0..120
    int tn = (tid & 15) << 3;     // 0..120

    unsigned long long acc2[8][4];
#pragma unroll
    for (int i = 0; i < 8; i++)
#pragma unroll
        for (int j = 0; j < 4; j++) acc2[i][j] = 0ull;

    for (int k0 = 0; k0 < E_; k0 += BK) {
#pragma unroll
        for (int it = 0; it < 2; it++) {
            int t = tid + it * 256;        // 0..511
            int row = t >> 2;              // 0..127
            int kq = (t & 3) << 2;         // 0,4,8,12
            int mp = m0 + row;
            int bb = mp & 63, ssx = mp >> 6;
            float4 va = *(const float4*)(X + ((long long)bb * S_ + ssx) * E_ + k0 + kq);
            As[kq + 0][row] = va.x; As[kq + 1][row] = va.y;
            As[kq + 2][row] = va.z; As[kq + 3][row] = va.w;
            float4 vb = *(const float4*)(U + (long long)(n0 + row) * E_ + k0 + kq);
            Bs[kq + 0][row] = vb.x; Bs[kq + 1][row] = vb.y;
            Bs[kq + 2][row] = vb.z; Bs[kq + 3][row] = vb.w;
        }
        __syncthreads();
#pragma unroll
        for (int k = 0; k < BK; k++) {
            float4 a0 = *(const float4*)&As[k][tm];
            float4 a1 = *(const float4*)&As[k][tm + 4];
            ulonglong2 bL = *(const ulonglong2*)&Bs[k][tn];
            ulonglong2 bH = *(const ulonglong2*)&Bs[k][tn + 4];
            unsigned long long ap[8];
            PACKDUP(ap[0], a0.x); PACKDUP(ap[1], a0.y);
            PACKDUP(ap[2], a0.z); PACKDUP(ap[3], a0.w);
            PACKDUP(ap[4], a1.x); PACKDUP(ap[5], a1.y);
            PACKDUP(ap[6], a1.z); PACKDUP(ap[7], a1.w);
#pragma unroll
            for (int i = 0; i < 8; i++) {
                FMA2(acc2[i][0], ap[i], bL.x);
                FMA2(acc2[i][1], ap[i], bL.y);
                FMA2(acc2[i][2], ap[i], bH.x);
                FMA2(acc2[i][3], ap[i], bH.y);
            }
        }
        __syncthreads();
    }

    float acc[8][8];
#pragma unroll
    for (int i = 0; i < 8; i++)
#pragma unroll
        for (int jp = 0; jp < 4; jp++)
            UNPACK2(acc[i][2 * jp], acc[i][2 * jp + 1], acc2[i][jp]);

    int ssx = (m0 + tm) >> 6;
    int b0  = (m0 + tm) & 63;     // 8 consecutive b, same s
#pragma unroll
    for (int j = 0; j < 8; j++) {
        int g = n0 + tn + j;
        float ub = Ub[g];
        float4 v0, v1;
        v0.x = acc[0][j] + ub; v0.y = acc[1][j] + ub; v0.z = acc[2][j] + ub; v0.w = acc[3][j] + ub;
        v1.x = acc[4][j] + ub; v1.y = acc[5][j] + ub; v1.z = acc[6][j] + ub; v1.w = acc[7][j] + ub;
        float* dst = &g_upT[((long long)ssx * 2048 + g) * 64 + b0];
        *(float4*)dst = v0;
        *(float4*)(dst + 4) = v1;
    }
}

// ---------------- persistent recurrent kernel ----------------
// SMEM floats: ws[512*20] | buf[2][ h:128*64 | c:128*64 ] | red[4*20*64] | hn[256] | cn[256] | mbar(4)
#define SM_WS   0
#define SM_BUF  (512 * 20)                    // 10240
#define SM_RED  (SM_BUF + 2 * 16384)          // 43008
#define SM_HN   (SM_RED + 4 * 20 * 64)        // 48128
#define SM_CN   (SM_HN + 256)                 // 48384
#define SM_MBAR (SM_CN + 256)                 // 48640 (16B aligned)
#define SM_FLOATS (SM_MBAR + 4)

__global__ __launch_bounds__(NTHR, 1) void step_kernel(
    const float* __restrict__ Wall, const float* __restrict__ Wallb,
    const float* __restrict__ Wd,   const float* __restrict__ Wdb,
    float* __restrict__ out)
{
    extern __shared__ float sm[];
    float* ws  = sm + SM_WS;
    float* red = sm + SM_RED;
    float* hn  = sm + SM_HN;
    float* cn  = sm + SM_CN;

    const int tid  = threadIdx.x;
    const int cta  = blockIdx.x;
    const int kgrp = tid / 80;          // 0..3
    const int r80  = tid % 80;
    const int rgrp = r80 / 16;          // 0..4   (0..3 -> gate rows, 4 -> decay rows)
    const int bgrp = r80 % 16;          // 0..15
    const int u0   = cta * 4;           // this CTA's 4 hidden units

    const unsigned mbar0 = smem_u32(sm + SM_MBAR);
    const unsigned mbar1 = mbar0 + 8;
    const unsigned bufA  = smem_u32(sm + SM_BUF);

    if (tid == 0) { mbar_init(mbar0, 1); mbar_init(mbar1, 1); }

    // ---- load this CTA's 20 weight rows into SMEM (once), layout ws[k*20 + rloc] ----
    for (int i = tid; i < 20 * 512; i += NTHR) {
        int rloc = i >> 9, k = i & 511;
        float w;
        if (rloc < 16) w = Wall[((rloc >> 2) * 512 + u0 + (rloc & 3)) * 512 + k];
        else           w = Wd[(u0 + (rloc - 16)) * 512 + k];
        ws[k * 20 + rloc] = w;
    }

    // ---- epilogue cell ownership: thread t<256 owns (b = t&63, ul = t>>6) ----
    const int  eb  = tid & 63;
    const int  eul = tid >> 6;
    const bool ep  = (tid < 256);
    const int  eu  = u0 + eul;
    float c_reg = 0.0f;
    float bf = 0, bi = 0, bo = 0, bct = 0, bd = 0;
    if (ep) {
        bf  = Wallb[eu];
        bi  = Wallb[512 + eu];
        bo  = Wallb[1024 + eu];
        bct = Wallb[1536 + eu];
        bd  = Wdb[eu];
    }
    __syncthreads();

    // within-chunk A base offset for this thread (h section or c section)
    const int asec  = (rgrp < 4) ? 0 : (128 * 64);
    const int aoff  = asec + kgrp * 32 * 64 + bgrp * 4;
    const int woff  = rgrp * 4;

    for (int s = 0; s < S_; s++) {
        const int par = s & 1;
        const float* gh = g_h[par];
        const float* gc = g_c[par];

        // ---- prefetch epilogue operands early (hide DRAM latency under GEMM) ----
        float upf = 0, upi = 0, upo = 0, upc = 0, dec = 0;
        if (ep) {
            const float* up = &g_upT[(long long)s * 2048 * 64];
            upf = __ldcs(&up[(0 * 512 + eu) * 64 + eb]);
            upi = __ldcs(&up[(1 * 512 + eu) * 64 + eb]);
            upo = __ldcs(&up[(2 * 512 + eu) * 64 + eb]);
            upc = __ldcs(&up[(3 * 512 + eu) * 64 + eb]);
            dec = g_decT[s * 64 + eb];
        }

        // ---- kick off TMA for chunk 0 ----
        if (tid == 0) {
            mbar_expect(mbar0, 65536);
            bulk_g2s(bufA, gh, 32768, mbar0);
            bulk_g2s(bufA + 32768, gc, 32768, mbar0);
        }

        unsigned long long acc2[4][2];
#pragma unroll
        for (int i = 0; i < 4; i++) { acc2[i][0] = 0ull; acc2[i][1] = 0ull; }

        for (int c = 0; c < 4; c++) {
            const int bi2 = c & 1;
            const unsigned mb = bi2 ? mbar1 : mbar0;
            mbar_wait(mb, (unsigned)((c >> 1) & 1));
            __syncthreads();      // all threads done reading buf[1-bi2] (chunk c-1)

            if (c < 3 && tid == 0) {
                const int nb = (c + 1) & 1;
                const unsigned mb2 = nb ? mbar1 : mbar0;
                mbar_expect(mb2, 65536);
                unsigned dst = bufA + nb * 65536;
                bulk_g2s(dst, gh + (c + 1) * 128 * 64, 32768, mb2);
                bulk_g2s(dst + 32768, gc + (c + 1) * 128 * 64, 32768, mb2);
            }

            const float* ab = sm + SM_BUF + bi2 * 16384 + aoff;
            const float* wb = ws + (c * 128 + kgrp * 32) * 20 + woff;
#pragma unroll 16
            for (int kk = 0; kk < 32; kk++) {
                float4 a4 = *(const float4*)(ab + kk * 64);
                ulonglong2 w2 = *(const ulonglong2*)(wb + kk * 20);
                unsigned long long a0p, a1p, a2p, a3p;
                PACKDUP(a0p, a4.x); PACKDUP(a1p, a4.y);
                PACKDUP(a2p, a4.z); PACKDUP(a3p, a4.w);
                FMA2(acc2[0][0], a0p, w2.x); FMA2(acc2[0][1], a0p, w2.y);
                FMA2(acc2[1][0], a1p, w2.x); FMA2(acc2[1][1], a1p, w2.y);
                FMA2(acc2[2][0], a2p, w2.x); FMA2(acc2[2][1], a2p, w2.y);
                FMA2(acc2[3][0], a3p, w2.x); FMA2(acc2[3][1], a3p, w2.y);
            }
        }

        // ---- K-group reduce via SMEM ----
        float accf[4][4];
#pragma unroll
        for (int i = 0; i < 4; i++) {
            UNPACK2(accf[i][0], accf[i][1], acc2[i][0]);
            UNPACK2(accf[i][2], accf[i][3], acc2[i][1]);
        }
#pragma unroll
        for (int j = 0; j < 4; j++) {
            float4 v;
            v.x = accf[0][j]; v.y = accf[1][j]; v.z = accf[2][j]; v.w = accf[3][j];
            *(float4*)&red[(kgrp * 20 + rgrp * 4 + j) * 64 + bgrp * 4] = v;
        }
        __syncthreads();

        // ---- fused LSTM update epilogue ----
        if (ep) {
            float gsum[5];
#pragma unroll
            for (int g5 = 0; g5 < 5; g5++) {
                int rl = (g5 < 4) ? (g5 * 4 + eul) : (16 + eul);
                float v = 0.0f;
#pragma unroll
                for (int kg = 0; kg < 4; kg++) v += red[(kg * 20 + rl) * 64 + eb];
                gsum[g5] = v;
            }
            float cs1  = tanh_fast(gsum[4] + bd);
            float cadj = (c_reg - cs1) + cs1 * dec;
            float f  = sigf(gsum[0] + bf + upf);
            float ii = sigf(gsum[1] + bi + upi);
            float oo = sigf(gsum[2] + bo + upo);
            float ct = tanh_fast(gsum[3] + bct + upc);
            float cnew = f * cadj + ii * ct;
            float hnew = oo * tanh_fast(cnew);
            c_reg = cnew;

            int par2 = par ^ 1;
            __stcg(&g_h[par2][eu * 64 + eb], hnew);
            __stcg(&g_c[par2][eu * 64 + eb], cnew);
            hn[eb * 4 + eul] = hnew;
            cn[eb * 4 + eul] = cnew;
        }
        __syncthreads();

        // coalesced-ish output writes via SMEM bounce (16B per store)
        if (tid < 64) {
            float4 hv = *(float4*)&hn[tid * 4];
            *(float4*)&out[((long long)tid * S_ + s) * H_ + u0] = hv;
            if (s == S_ - 1) {
                float4 cv = *(float4*)&cn[tid * 4];
                *(float4*)&out[(long long)B_ * S_ * H_ + (long long)tid * H_ + u0] = hv;
                *(float4*)&out[(long long)B_ * S_ * H_ + (long long)B_ * H_ + (long long)tid * H_ + u0] = cv;
            }
        }

        grid_barrier();   // h/c parity buffers published for next step
    }
}

// ---------------- launcher ----------------
extern "C" void kernel_launch(void* const* d_in, const int* in_sizes, int n_in,
                              void* d_out, int out_size) {
    const float* inputs = (const float*)d_in[0];
    const float* ts     = (const float*)d_in[1];
    const float* Wall   = (const float*)d_in[2];
    const float* Wallb  = (const float*)d_in[3];
    const float* U      = (const float*)d_in[4];
    const float* Ub     = (const float*)d_in[5];
    const float* Wd     = (const float*)d_in[6];
    const float* Wdb    = (const float*)d_in[7];
    float* out = (float*)d_out;

    prep_kernel<<<(S_ * B_ + 255) / 256, 256>>>(ts);

    dim3 ggrid(32768 / BM, 2048 / BN);
    uproj_gemm<<<ggrid, 256>>>(inputs, U, Ub);

    static const size_t smem_bytes = (size_t)SM_FLOATS * sizeof(float);  // ~190 KB
    cudaFuncSetAttribute(step_kernel, cudaFuncAttributeMaxDynamicSharedMemorySize,
                         (int)smem_bytes);
    step_kernel<<<NCTA, NTHR, smem_bytes>>>(Wall, Wallb, Wd, Wdb, out);
}